// round 12
// baseline (speedup 1.0000x reference)
#include <cuda_runtime.h>
#include <cuda_fp16.h>
#include <math.h>
#include <stdint.h>

#define T_STEPS 256
#define B_DIM   128
#define H_DIM   2048

// ---- xproj tiling (KC=64) ----
#define KC      64
#define NCH     (H_DIM / KC)       // 32
#define ROWB    144                // 64 fp16 + 16B pad

// ---- scan tiling (KC3=256, 2-stage) ----
#define KC3     256
#define NCH3    (H_DIM / KC3)      // 8
#define ROWB3   528                // 256 fp16 + 16B pad (4-bank row stagger)

// ---- persistent scan kernel smem ----
#define WPITCH   4112              // 2048*2 + 16 pad: conflict-free ldsm rows
#define WH_SZ    (32 * WPITCH)     // 131584 B resident W^T slice (fp16)
#define ST_SZ    (64 * ROWB3)      // 33792 B per h stage
#define SMEM_SCAN (WH_SZ + 2 * ST_SZ)   // 199168 (2-stage)

// ---- xproj kernel smem (1-product, A converted in-kernel) ----
#define X_A   0                    // x tile (fp16): 128*144 = 18432
#define X_B   18432                // W_in: 64*144 = 9216
#define X_STG 27648
#define SMEM_XPROJ (3 * X_STG)     // 82944

// ---------------------------------------------------------------------------
// Device scratch (no allocations allowed anywhere)
// ---------------------------------------------------------------------------
__device__ __align__(128) float  g_xproj[(size_t)T_STEPS * B_DIM * H_DIM];  // 256 MB
__device__ __align__(128) __half g_h[2][B_DIM * H_DIM];                     // fp16 hidden
__device__ __align__(128) __half g_wr[(size_t)H_DIM * H_DIM];               // w_rec^T fp16
__device__ __align__(128) __half g_wi[(size_t)H_DIM * H_DIM];               // w_in^T fp16
__device__ unsigned g_bar[2 * T_STEPS];                                     // per-(t, mh) counters

// ---------------------------------------------------------------------------
// PTX helpers — legal on plain sm_103 target
// ---------------------------------------------------------------------------
__device__ __forceinline__ uint32_t smem_u32(const void* p) {
    uint32_t a;
    asm("{ .reg .u64 t; cvta.to.shared.u64 t, %1; cvt.u32.u64 %0, t; }"
        : "=r"(a) : "l"(p));
    return a;
}
__device__ __forceinline__ void cp16(uint32_t dst, const void* src) {
    asm volatile("cp.async.cg.shared.global [%0], [%1], 16;"
                 :: "r"(dst), "l"(src) : "memory");
}
__device__ __forceinline__ void cp_commit() {
    asm volatile("cp.async.commit_group;" ::: "memory");
}
__device__ __forceinline__ void cp_wait1() {
    asm volatile("cp.async.wait_group 1;" ::: "memory");
}
__device__ __forceinline__ void cp_wait0() {
    asm volatile("cp.async.wait_group 0;" ::: "memory");
}
__device__ __forceinline__ void ldsm4(uint32_t addr, uint32_t r[4]) {
    asm volatile("ldmatrix.sync.aligned.m8n8.x4.shared.b16 {%0,%1,%2,%3}, [%4];"
                 : "=r"(r[0]), "=r"(r[1]), "=r"(r[2]), "=r"(r[3]) : "r"(addr));
}
__device__ __forceinline__ void mma16816(float c[4], const uint32_t a[4],
                                         uint32_t b0, uint32_t b1) {
    asm volatile("mma.sync.aligned.m16n8k16.row.col.f32.f16.f16.f32 "
                 "{%0,%1,%2,%3},{%4,%5,%6,%7},{%8,%9},{%0,%1,%2,%3};"
                 : "+f"(c[0]), "+f"(c[1]), "+f"(c[2]), "+f"(c[3])
                 : "r"(a[0]), "r"(a[1]), "r"(a[2]), "r"(a[3]), "r"(b0), "r"(b1));
}
__device__ __forceinline__ void sts128(uint32_t dst, uint32_t a, uint32_t b,
                                       uint32_t c, uint32_t d) {
    asm volatile("st.shared.v4.b32 [%0], {%1,%2,%3,%4};"
                 :: "r"(dst), "r"(a), "r"(b), "r"(c), "r"(d) : "memory");
}

// ---------------------------------------------------------------------------
// FMA-only accurate tanh, |err| ~2e-7
// ---------------------------------------------------------------------------
__device__ __forceinline__ float fast_tanh(float x) {
    float ax = fminf(fabsf(x), 9.0f);
    float t  = ax * 2.8853900817779268f;
    float f  = t + 12582912.0f;
    int   n  = __float_as_int(f) - 0x4B400000;
    float r  = t - (f - 12582912.0f);
    float p = 1.5403530e-4f;
    p = fmaf(p, r, 1.3333558e-3f);
    p = fmaf(p, r, 9.6181291e-3f);
    p = fmaf(p, r, 5.5504109e-2f);
    p = fmaf(p, r, 2.4022651e-1f);
    p = fmaf(p, r, 6.9314718e-1f);
    p = fmaf(p, r, 1.0f);
    float e2x = p * __int_as_float((n + 127) << 23);
    float d = e2x + 1.0f;
    float rc = __int_as_float(0x7EF311C3 - __float_as_int(d));
    rc = rc * fmaf(-d, rc, 2.0f);
    rc = rc * fmaf(-d, rc, 2.0f);
    rc = rc * fmaf(-d, rc, 2.0f);
    float y = fmaf(-2.0f, rc, 1.0f);
    return __int_as_float(__float_as_int(y) | (__float_as_int(x) & 0x80000000));
}

// ---------------------------------------------------------------------------
// Prep kernels
// ---------------------------------------------------------------------------
__global__ void init_h0_kernel() {
    int i = blockIdx.x * blockDim.x + threadIdx.x;
    if (i < B_DIM * H_DIM) g_h[0][i] = __float2half(0.0f);
    if (i < 2 * T_STEPS) g_bar[i] = 0u;
}

// Both weight transposes in one launch: z=0 -> w_rec->g_wr, z=1 -> w_in->g_wi.
// W (k,n) fp32 -> W^T (n,k) single fp16. 32x32 tiles.
__global__ __launch_bounds__(256) void wtrans2_kernel(
    const float* __restrict__ Wr, const float* __restrict__ Wi)
{
    __shared__ float tile[32][33];
    const float* __restrict__ W = blockIdx.z ? Wi : Wr;
    __half* __restrict__ d = blockIdx.z ? g_wi : g_wr;
    int tx = threadIdx.x, ty = threadIdx.y;
    int k0 = blockIdx.y * 32;
    int n0 = blockIdx.x * 32;
    #pragma unroll
    for (int j = 0; j < 32; j += 8)
        tile[ty + j][tx] = W[(size_t)(k0 + ty + j) * H_DIM + n0 + tx];
    __syncthreads();
    #pragma unroll
    for (int j = 0; j < 32; j += 8) {
        size_t idx = (size_t)(n0 + ty + j) * H_DIM + k0 + tx;
        d[idx] = __float2half(tile[tx][ty + j]);
    }
}

// ---------------------------------------------------------------------------
// xproj = X @ W_in + bias  (fp16 1-product HMMA, 3-stage pipeline).
// A (x) is read as fp32 DIRECTLY from the input and converted to fp16 in the
// load path: LDG to registers one chunk ahead, cvt+STS the chunk after.
// CTA tile 128x64, 8 warps (4m x 2n), warp tile 32x32. Grid (32, 256).
// ---------------------------------------------------------------------------
__global__ __launch_bounds__(256) void xproj_mma_kernel(
    const float* __restrict__ x, const float* __restrict__ bias)
{
    extern __shared__ char smem[];
    const uint32_t sb = smem_u32(smem);
    const int tid = threadIdx.x, wid = tid >> 5, lane = tid & 31;
    const int m0 = blockIdx.y * 128;
    const int n0 = blockIdx.x * 64;

    const float* __restrict__ A = x + (size_t)m0 * H_DIM;
    const __half* __restrict__ B = g_wi + (size_t)n0 * H_DIM;

    // A-conversion mapping: thread owns row r = tid>>1, half = tid&1 (32 cols)
    const int arow = tid >> 1, ahalf = tid & 1;
    const float* __restrict__ asrc = A + (size_t)arow * H_DIM + ahalf * 32;
    const uint32_t adst = (uint32_t)(arow * ROWB + ahalf * 64);

    float4 xr[8];                                  // chunk staging (32 floats)
    auto ldg_A = [&](int cch) {
        const float* s = asrc + cch * KC;
        #pragma unroll
        for (int j = 0; j < 8; j++) xr[j] = __ldg((const float4*)(s + j * 4));
    };
    auto sts_A = [&](int s) {
        uint32_t dst = sb + s * X_STG + X_A + adst;
        #pragma unroll
        for (int j = 0; j < 8; j += 2) {
            __half2 h0 = __floats2half2_rn(xr[j].x, xr[j].y);
            __half2 h1 = __floats2half2_rn(xr[j].z, xr[j].w);
            __half2 h2 = __floats2half2_rn(xr[j + 1].x, xr[j + 1].y);
            __half2 h3 = __floats2half2_rn(xr[j + 1].z, xr[j + 1].w);
            sts128(dst + j * 8, *(uint32_t*)&h0, *(uint32_t*)&h1,
                   *(uint32_t*)&h2, *(uint32_t*)&h3);
        }
    };
    auto cpB = [&](int s, int cch) {
        const int k0 = cch * KC;
        uint32_t base = sb + s * X_STG;
        #pragma unroll
        for (int j = 0; j < 2; j++) {              // B: 64 rows x 8 chunks
            int idx = tid + j * 256;
            int r = idx >> 3, kc = idx & 7;
            cp16(base + X_B + r * ROWB + kc * 16, B + (size_t)r * H_DIM + k0 + kc * 8);
        }
        cp_commit();
    };

    float c[2][4][4];
    #pragma unroll
    for (int i = 0; i < 2; i++)
        #pragma unroll
        for (int j = 0; j < 4; j++)
            #pragma unroll
            for (int q = 0; q < 4; q++) c[i][j][q] = 0.0f;

    const int mwb = (wid >> 1) * 32;
    const int nwb = (wid & 1) * 32;
    const uint32_t aOff = (uint32_t)((lane & 15) * ROWB + (lane >> 4) * 16);
    const uint32_t bOff = (uint32_t)(((lane & 7) | ((lane >> 1) & 8)) * ROWB + (lane & 8) * 2);

    auto compute_stage = [&](int s) {
        uint32_t base = sb + s * X_STG;
        uint32_t aA = base + X_A + mwb * ROWB + aOff;
        uint32_t bB = base + X_B + nwb * ROWB + bOff;
        uint32_t ah[2][2][4], bh[2][8];
        ldsm4(aA, ah[0][0]);
        ldsm4(aA + 16 * ROWB, ah[0][1]);
        ldsm4(bB, bh[0]);
        ldsm4(bB + 16 * ROWB, bh[0] + 4);
        #pragma unroll
        for (int kk = 0; kk < KC / 16; kk++) {
            int cur = kk & 1, nxt = cur ^ 1;
            if (kk + 1 < KC / 16) {                // prefetch next k16 fragments
                ldsm4(aA + (kk + 1) * 32, ah[nxt][0]);
                ldsm4(aA + 16 * ROWB + (kk + 1) * 32, ah[nxt][1]);
                ldsm4(bB + (kk + 1) * 32, bh[nxt]);
                ldsm4(bB + 16 * ROWB + (kk + 1) * 32, bh[nxt] + 4);
            }
            #pragma unroll
            for (int mi = 0; mi < 2; mi++)
                #pragma unroll
                for (int ni = 0; ni < 4; ni++)
                    mma16816(c[mi][ni], ah[cur][mi], bh[cur][2 * ni], bh[cur][2 * ni + 1]);
        }
    };

    // prologue: stage chunks 0 and 1; xr holds chunk 2 entering the loop
    ldg_A(0); sts_A(0); cpB(0, 0);
    ldg_A(1); sts_A(1); cpB(1, 1);
    ldg_A(2);

    #pragma unroll 1
    for (int cch = 0; cch < NCH; cch++) {
        if (cch == NCH - 1) cp_wait0(); else cp_wait1();
        __syncthreads();
        if (cch + 2 < NCH) {
            cpB((cch + 2) % 3, cch + 2);
            sts_A((cch + 2) % 3);                  // xr = chunk cch+2
        }
        if (cch + 3 < NCH) ldg_A(cch + 3);         // refill xr for next iter
        compute_stage(cch % 3);
    }

    #pragma unroll
    for (int mi = 0; mi < 2; mi++)
        #pragma unroll
        for (int ni = 0; ni < 4; ni++) {
            int r  = m0 + mwb + mi * 16 + (lane >> 2);
            int cc = n0 + nwb + ni * 8 + 2 * (lane & 3);
            float bx = bias[cc], by = bias[cc + 1];
            size_t o0 = (size_t)r * H_DIM + cc;
            size_t o1 = o0 + (size_t)8 * H_DIM;
            *(float2*)(g_xproj + o0) = make_float2(c[mi][ni][0] + bx, c[mi][ni][1] + by);
            *(float2*)(g_xproj + o1) = make_float2(c[mi][ni][2] + bx, c[mi][ni][3] + by);
        }
}

// ---------------------------------------------------------------------------
// Persistent scan kernel (R10 structure — best measured): all 256 steps in
// ONE launch. Grid (64, 2) = 128 CTAs, 128 threads (4 warps, 2m x 2n, warp
// tile 32x16). W^T slice resident; h streamed via 2-stage cp.async pipeline
// (KC3=256 -> 8 chunks, 8 CTA syncs/step); register double-buffered
// ldsm/mma; xproj prefetch hoisted above the per-mh 64-CTA barrier.
// ---------------------------------------------------------------------------
__global__ __launch_bounds__(128) void scan_kernel(float* __restrict__ final_out) {
    extern __shared__ char smem[];
    const uint32_t sb = smem_u32(smem);
    const int tid = threadIdx.x, wid = tid >> 5, lane = tid & 31;
    const int nt = blockIdx.x, mh = blockIdx.y;
    const int n0 = nt * 32;
    const int m0 = mh * 64;

    // ---- load resident W^T slice (32 rows x 2048 k), pitch 4112 ----
    {
        const __half* Wg = g_wr + (size_t)n0 * H_DIM;
        #pragma unroll 4
        for (int idx = tid; idx < 32 * 256; idx += 128) {      // 16B units
            int r = idx >> 8, kc = idx & 255;
            cp16(sb + r * WPITCH + kc * 16, Wg + (size_t)r * H_DIM + kc * 8);
        }
        cp_commit();
        cp_wait0();
        __syncthreads();
    }

    const int wm = wid >> 1, wn = wid & 1;
    const uint32_t aOff   = (uint32_t)((lane & 15) * ROWB3 + (lane >> 4) * 16);
    const uint32_t rowsel = (uint32_t)((lane & 7) | ((lane >> 1) & 8));
    const uint32_t bOffH  = rowsel * WPITCH + (lane & 8) * 2 + (uint32_t)(wn * 16) * WPITCH;

    const int er  = m0 + wm * 32 + (lane >> 2);
    const int ecc = n0 + wn * 16 + 2 * (lane & 3);
    const size_t eo00 = (size_t)er * H_DIM + ecc;              // (mi=0, ni=0)

    // ---- prefetch xproj fragment for t=0 ----
    float2 xf[2][2][2];
    {
        const float* __restrict__ xp0 = g_xproj;
        #pragma unroll
        for (int mi = 0; mi < 2; mi++)
            #pragma unroll
            for (int ni = 0; ni < 2; ni++) {
                size_t o0 = eo00 + (size_t)(mi * 16) * H_DIM + ni * 8;
                xf[mi][ni][0] = __ldg((const float2*)(xp0 + o0));
                xf[mi][ni][1] = __ldg((const float2*)(xp0 + o0 + (size_t)8 * H_DIM));
            }
    }

    for (int t = 0; t < T_STEPS; t++) {
        const __half* __restrict__ Ahg = g_h[t & 1] + (size_t)m0 * H_DIM;

        float c[2][2][4];
        #pragma unroll
        for (int i = 0; i < 2; i++)
            #pragma unroll
            for (int j = 0; j < 2; j++)
                #pragma unroll
                for (int q = 0; q < 4; q++) c[i][j][q] = 0.0f;

        auto load_stage = [&](int s, int cch) {
            const int k0 = cch * KC3;
            uint32_t base = sb + WH_SZ + s * ST_SZ;
            #pragma unroll
            for (int j = 0; j < 16; j++) {         // h: 64 rows x 32 chunks of 16B
                int idx = tid + j * 128;
                int r = idx >> 5, kc = idx & 31;
                cp16(base + r * ROWB3 + kc * 16,
                     Ahg + (size_t)r * H_DIM + k0 + kc * 8);
            }
            cp_commit();
        };

        auto compute_stage = [&](int s, int cch) {
            uint32_t base = sb + WH_SZ + s * ST_SZ;
            uint32_t aA = base + (uint32_t)(wm * 32) * ROWB3 + aOff;
            uint32_t bH = sb + bOffH + (uint32_t)(cch * KC3) * 2;
            uint32_t ah[2][2][4], bh[2][4];
            ldsm4(aA, ah[0][0]);
            ldsm4(aA + 16 * ROWB3, ah[0][1]);
            ldsm4(bH, bh[0]);
            #pragma unroll
            for (int kk = 0; kk < KC3 / 16; kk++) {
                int cur = kk & 1, nxt = cur ^ 1;
                if (kk + 1 < KC3 / 16) {           // prefetch next k16 fragments
                    ldsm4(aA + (kk + 1) * 32, ah[nxt][0]);
                    ldsm4(aA + 16 * ROWB3 + (kk + 1) * 32, ah[nxt][1]);
                    ldsm4(bH + (kk + 1) * 32, bh[nxt]);
                }
                #pragma unroll
                for (int mi = 0; mi < 2; mi++)
                    #pragma unroll
                    for (int ni = 0; ni < 2; ni++)
                        mma16816(c[mi][ni], ah[cur][mi], bh[cur][2 * ni], bh[cur][2 * ni + 1]);
            }
        };

        // ---- 2-stage pipeline, one sync per chunk, wait0 exact ----
        load_stage(0, 0);
        #pragma unroll 1
        for (int cch = 0; cch < NCH3; cch++) {
            cp_wait0();
            __syncthreads();
            if (cch + 1 < NCH3) load_stage((cch + 1) & 1, cch + 1);
            compute_stage(cch & 1, cch);
        }

        // ---- epilogue: tanh(acc + xproj_t) -> h fp16 (or final fp32) ----
        const bool last = (t == T_STEPS - 1);
        __half* __restrict__ Hn = g_h[(t + 1) & 1];

        #pragma unroll
        for (int mi = 0; mi < 2; mi++)
            #pragma unroll
            for (int ni = 0; ni < 2; ni++) {
                size_t o0 = eo00 + (size_t)(mi * 16) * H_DIM + ni * 8;
                size_t o1 = o0 + (size_t)8 * H_DIM;
                float2 x0 = xf[mi][ni][0];
                float2 x1 = xf[mi][ni][1];
                float v00 = fast_tanh(c[mi][ni][0] + x0.x);
                float v01 = fast_tanh(c[mi][ni][1] + x0.y);
                float v10 = fast_tanh(c[mi][ni][2] + x1.x);
                float v11 = fast_tanh(c[mi][ni][3] + x1.y);
                if (last) {
                    *(float2*)(final_out + o0) = make_float2(v00, v01);
                    *(float2*)(final_out + o1) = make_float2(v10, v11);
                } else {
                    *(__half2*)(Hn + o0) = __floats2half2_rn(v00, v01);
                    *(__half2*)(Hn + o1) = __floats2half2_rn(v10, v11);
                }
            }

        if (!last) {
            // ---- prefetch xproj for t+1 BEFORE the barrier (h-independent) ----
            const float* __restrict__ xpn = g_xproj + (size_t)(t + 1) * B_DIM * H_DIM;
            #pragma unroll
            for (int mi = 0; mi < 2; mi++)
                #pragma unroll
                for (int ni = 0; ni < 2; ni++) {
                    size_t o0 = eo00 + (size_t)(mi * 16) * H_DIM + ni * 8;
                    xf[mi][ni][0] = __ldg((const float2*)(xpn + o0));
                    xf[mi][ni][1] = __ldg((const float2*)(xpn + o0 + (size_t)8 * H_DIM));
                }

            // ---- per-mh grid barrier (64 CTAs), release/acquire ----
            __syncthreads();
            if (tid == 0) {
                unsigned* bp = &g_bar[2 * t + mh];
                asm volatile("red.release.gpu.global.add.u32 [%0], %1;"
                             :: "l"(bp), "r"(1u) : "memory");
                unsigned v;
                do {
                    asm volatile("ld.acquire.gpu.global.u32 %0, [%1];"
                                 : "=r"(v) : "l"(bp) : "memory");
                } while (v < 64u);
            }
            __syncthreads();
        }
    }
}

// ---------------------------------------------------------------------------
// Host launch — plain kernel launches only, graph-capturable
// ---------------------------------------------------------------------------
extern "C" void kernel_launch(void* const* d_in, const int* in_sizes, int n_in,
                              void* d_out, int out_size)
{
    const float* x     = (const float*)d_in[0];
    const float* w_in  = (const float*)d_in[1];
    const float* w_rec = (const float*)d_in[2];
    const float* bias  = (const float*)d_in[3];
    float* out = (float*)d_out;

    cudaFuncSetAttribute(scan_kernel,
                         cudaFuncAttributeMaxDynamicSharedMemorySize, SMEM_SCAN);
    cudaFuncSetAttribute(xproj_mma_kernel,
                         cudaFuncAttributeMaxDynamicSharedMemorySize, SMEM_XPROJ);

    // prep
    init_h0_kernel<<<(B_DIM * H_DIM + 255) / 256, 256>>>();
    wtrans2_kernel<<<dim3(H_DIM / 32, H_DIM / 32, 2), dim3(32, 8)>>>(w_rec, w_in);

    // xproj (tensor-core, 1-product fp16; fused x conversion)
    xproj_mma_kernel<<<dim3(H_DIM / 64, (T_STEPS * B_DIM) / 128), 256, SMEM_XPROJ>>>(x, bias);

    // persistent scan: all 256 steps in one launch
    scan_kernel<<<dim3(H_DIM / 32, B_DIM / 64), 128, SMEM_SCAN>>>(out);
}

// round 13
// speedup vs baseline: 1.5121x; 1.5121x over previous
#include <cuda_runtime.h>
#include <cuda_fp16.h>
#include <math.h>
#include <stdint.h>

#define T_STEPS 256
#define B_DIM   128
#define H_DIM   2048

// ---- xproj tiling (KC=64) ----
#define KC      64
#define NCH     (H_DIM / KC)       // 32
#define ROWB    144                // 64 fp16 + 16B pad

// ---- scan tiling (KC3=256, 2-stage) ----
#define KC3     256
#define NCH3    (H_DIM / KC3)      // 8
#define ROWB3   528                // 256 fp16 + 16B pad (4-bank row stagger)

// ---- persistent scan kernel smem ----
#define WPITCH   4112              // 2048*2 + 16 pad: conflict-free ldsm rows
#define WH_SZ    (32 * WPITCH)     // 131584 B resident W^T slice (fp16)
#define ST_SZ    (64 * ROWB3)      // 33792 B per h stage
#define SMEM_SCAN (WH_SZ + 2 * ST_SZ)   // 199168 (2-stage)

// ---- xproj kernel smem (1-product) ----
#define X_A   0                    // x tile (fp16): 128*144 = 18432
#define X_B   18432                // W_in: 64*144 = 9216
#define X_STG 27648
#define SMEM_XPROJ (3 * X_STG)     // 82944

// ---------------------------------------------------------------------------
// Device scratch (no allocations allowed anywhere)
// ---------------------------------------------------------------------------
__device__ __align__(128) __half g_xproj[(size_t)T_STEPS * B_DIM * H_DIM];  // 128 MB (fp16)
__device__ __align__(128) __half g_h[2][B_DIM * H_DIM];                     // fp16 hidden
__device__ __align__(128) __half g_wr[(size_t)H_DIM * H_DIM];               // w_rec^T fp16
__device__ __align__(128) __half g_wi[(size_t)H_DIM * H_DIM];               // w_in^T fp16
__device__ __align__(128) __half g_x[(size_t)T_STEPS * B_DIM * H_DIM];      // x fp16
__device__ unsigned g_bar[2 * T_STEPS];                                     // per-(t, mh) counters

// ---------------------------------------------------------------------------
// PTX helpers — legal on plain sm_103 target
// ---------------------------------------------------------------------------
__device__ __forceinline__ uint32_t smem_u32(const void* p) {
    uint32_t a;
    asm("{ .reg .u64 t; cvta.to.shared.u64 t, %1; cvt.u32.u64 %0, t; }"
        : "=r"(a) : "l"(p));
    return a;
}
__device__ __forceinline__ void cp16(uint32_t dst, const void* src) {
    asm volatile("cp.async.cg.shared.global [%0], [%1], 16;"
                 :: "r"(dst), "l"(src) : "memory");
}
__device__ __forceinline__ void cp_commit() {
    asm volatile("cp.async.commit_group;" ::: "memory");
}
__device__ __forceinline__ void cp_wait1() {
    asm volatile("cp.async.wait_group 1;" ::: "memory");
}
__device__ __forceinline__ void cp_wait0() {
    asm volatile("cp.async.wait_group 0;" ::: "memory");
}
__device__ __forceinline__ void ldsm4(uint32_t addr, uint32_t r[4]) {
    asm volatile("ldmatrix.sync.aligned.m8n8.x4.shared.b16 {%0,%1,%2,%3}, [%4];"
                 : "=r"(r[0]), "=r"(r[1]), "=r"(r[2]), "=r"(r[3]) : "r"(addr));
}
__device__ __forceinline__ void mma16816(float c[4], const uint32_t a[4],
                                         uint32_t b0, uint32_t b1) {
    asm volatile("mma.sync.aligned.m16n8k16.row.col.f32.f16.f16.f32 "
                 "{%0,%1,%2,%3},{%4,%5,%6,%7},{%8,%9},{%0,%1,%2,%3};"
                 : "+f"(c[0]), "+f"(c[1]), "+f"(c[2]), "+f"(c[3])
                 : "r"(a[0]), "r"(a[1]), "r"(a[2]), "r"(a[3]), "r"(b0), "r"(b1));
}

// ---------------------------------------------------------------------------
// FMA-only accurate tanh, |err| ~2e-7
// ---------------------------------------------------------------------------
__device__ __forceinline__ float fast_tanh(float x) {
    float ax = fminf(fabsf(x), 9.0f);
    float t  = ax * 2.8853900817779268f;
    float f  = t + 12582912.0f;
    int   n  = __float_as_int(f) - 0x4B400000;
    float r  = t - (f - 12582912.0f);
    float p = 1.5403530e-4f;
    p = fmaf(p, r, 1.3333558e-3f);
    p = fmaf(p, r, 9.6181291e-3f);
    p = fmaf(p, r, 5.5504109e-2f);
    p = fmaf(p, r, 2.4022651e-1f);
    p = fmaf(p, r, 6.9314718e-1f);
    p = fmaf(p, r, 1.0f);
    float e2x = p * __int_as_float((n + 127) << 23);
    float d = e2x + 1.0f;
    float rc = __int_as_float(0x7EF311C3 - __float_as_int(d));
    rc = rc * fmaf(-d, rc, 2.0f);
    rc = rc * fmaf(-d, rc, 2.0f);
    rc = rc * fmaf(-d, rc, 2.0f);
    float y = fmaf(-2.0f, rc, 1.0f);
    return __int_as_float(__float_as_int(y) | (__float_as_int(x) & 0x80000000));
}

// ---------------------------------------------------------------------------
// Prep kernels
// ---------------------------------------------------------------------------
__global__ void init_h0_kernel() {
    int i = blockIdx.x * blockDim.x + threadIdx.x;
    if (i < B_DIM * H_DIM) g_h[0][i] = __float2half(0.0f);
    if (i < 2 * T_STEPS) g_bar[i] = 0u;
}

// x (fp32) -> fp16, 8 elems per thread
__global__ __launch_bounds__(256) void conv_x_kernel(const float* __restrict__ x) {
    size_t i = ((size_t)blockIdx.x * blockDim.x + threadIdx.x) * 8;
    float4 v0 = *(const float4*)(x + i);
    float4 v1 = *(const float4*)(x + i + 4);
    __half2 h0 = __floats2half2_rn(v0.x, v0.y);
    __half2 h1 = __floats2half2_rn(v0.z, v0.w);
    __half2 h2 = __floats2half2_rn(v1.x, v1.y);
    __half2 h3 = __floats2half2_rn(v1.z, v1.w);
    *(uint4*)(g_x + i) = make_uint4(
        *(uint32_t*)&h0, *(uint32_t*)&h1, *(uint32_t*)&h2, *(uint32_t*)&h3);
}

// Both weight transposes in one launch: z=0 -> w_rec->g_wr, z=1 -> w_in->g_wi.
// W (k,n) fp32 -> W^T (n,k) single fp16. 32x32 tiles.
__global__ __launch_bounds__(256) void wtrans2_kernel(
    const float* __restrict__ Wr, const float* __restrict__ Wi)
{
    __shared__ float tile[32][33];
    const float* __restrict__ W = blockIdx.z ? Wi : Wr;
    __half* __restrict__ d = blockIdx.z ? g_wi : g_wr;
    int tx = threadIdx.x, ty = threadIdx.y;
    int k0 = blockIdx.y * 32;
    int n0 = blockIdx.x * 32;
    #pragma unroll
    for (int j = 0; j < 32; j += 8)
        tile[ty + j][tx] = W[(size_t)(k0 + ty + j) * H_DIM + n0 + tx];
    __syncthreads();
    #pragma unroll
    for (int j = 0; j < 32; j += 8) {
        size_t idx = (size_t)(n0 + ty + j) * H_DIM + k0 + tx;
        d[idx] = __float2half(tile[tx][ty + j]);
    }
}

// ---------------------------------------------------------------------------
// xproj = X @ W_in + bias  (fp16 1-product HMMA, 3-stage pipeline)
// CTA tile 128x64, 8 warps (4m x 2n), warp tile 32x32. Grid (32, 256).
// Output stored as fp16.
// ---------------------------------------------------------------------------
__global__ __launch_bounds__(256) void xproj_mma_kernel(const float* __restrict__ bias) {
    extern __shared__ char smem[];
    const uint32_t sb = smem_u32(smem);
    const int tid = threadIdx.x, wid = tid >> 5, lane = tid & 31;
    const int m0 = blockIdx.y * 128;
    const int n0 = blockIdx.x * 64;

    const __half* __restrict__ A = g_x + (size_t)m0 * H_DIM;
    const __half* __restrict__ B = g_wi + (size_t)n0 * H_DIM;

    float c[2][4][4];
    #pragma unroll
    for (int i = 0; i < 2; i++)
        #pragma unroll
        for (int j = 0; j < 4; j++)
            #pragma unroll
            for (int q = 0; q < 4; q++) c[i][j][q] = 0.0f;

    auto load_stage = [&](int s, int cch) {
        const int k0 = cch * KC;
        uint32_t base = sb + s * X_STG;
        #pragma unroll
        for (int j = 0; j < 4; j++) {              // A: 128 rows x 8 chunks
            int idx = tid + j * 256;
            int r = idx >> 3, kc = idx & 7;
            cp16(base + X_A + r * ROWB + kc * 16, A + (size_t)r * H_DIM + k0 + kc * 8);
        }
        #pragma unroll
        for (int j = 0; j < 2; j++) {              // B: 64 rows x 8 chunks
            int idx = tid + j * 256;
            int r = idx >> 3, kc = idx & 7;
            cp16(base + X_B + r * ROWB + kc * 16, B + (size_t)r * H_DIM + k0 + kc * 8);
        }
        cp_commit();
    };

    const int mwb = (wid >> 1) * 32;
    const int nwb = (wid & 1) * 32;
    const uint32_t aOff = (uint32_t)((lane & 15) * ROWB + (lane >> 4) * 16);
    const uint32_t bOff = (uint32_t)(((lane & 7) | ((lane >> 1) & 8)) * ROWB + (lane & 8) * 2);

    auto compute_stage = [&](int s) {
        uint32_t base = sb + s * X_STG;
        uint32_t aA = base + X_A + mwb * ROWB + aOff;
        uint32_t bB = base + X_B + nwb * ROWB + bOff;
        uint32_t ah[2][2][4], bh[2][8];
        ldsm4(aA, ah[0][0]);
        ldsm4(aA + 16 * ROWB, ah[0][1]);
        ldsm4(bB, bh[0]);
        ldsm4(bB + 16 * ROWB, bh[0] + 4);
        #pragma unroll
        for (int kk = 0; kk < KC / 16; kk++) {
            int cur = kk & 1, nxt = cur ^ 1;
            if (kk + 1 < KC / 16) {                // prefetch next k16 fragments
                ldsm4(aA + (kk + 1) * 32, ah[nxt][0]);
                ldsm4(aA + 16 * ROWB + (kk + 1) * 32, ah[nxt][1]);
                ldsm4(bB + (kk + 1) * 32, bh[nxt]);
                ldsm4(bB + 16 * ROWB + (kk + 1) * 32, bh[nxt] + 4);
            }
            #pragma unroll
            for (int mi = 0; mi < 2; mi++)
                #pragma unroll
                for (int ni = 0; ni < 4; ni++)
                    mma16816(c[mi][ni], ah[cur][mi], bh[cur][2 * ni], bh[cur][2 * ni + 1]);
        }
    };

    load_stage(0, 0);
    load_stage(1, 1);
    #pragma unroll 1
    for (int cch = 0; cch < NCH; cch++) {
        if (cch == NCH - 1) cp_wait0(); else cp_wait1();
        __syncthreads();
        if (cch + 2 < NCH) load_stage((cch + 2) % 3, cch + 2);
        compute_stage(cch % 3);
    }

    #pragma unroll
    for (int mi = 0; mi < 2; mi++)
        #pragma unroll
        for (int ni = 0; ni < 4; ni++) {
            int r  = m0 + mwb + mi * 16 + (lane >> 2);
            int cc = n0 + nwb + ni * 8 + 2 * (lane & 3);
            float bx = bias[cc], by = bias[cc + 1];
            size_t o0 = (size_t)r * H_DIM + cc;
            size_t o1 = o0 + (size_t)8 * H_DIM;
            *(__half2*)(g_xproj + o0) = __floats2half2_rn(c[mi][ni][0] + bx, c[mi][ni][1] + by);
            *(__half2*)(g_xproj + o1) = __floats2half2_rn(c[mi][ni][2] + bx, c[mi][ni][3] + by);
        }
}

// ---------------------------------------------------------------------------
// Persistent scan kernel (R10 structure — best measured): all 256 steps in
// ONE launch. Grid (64, 2) = 128 CTAs, 128 threads (4 warps, 2m x 2n, warp
// tile 32x16). W^T slice resident; h streamed via 2-stage cp.async pipeline
// (KC3=256 -> 8 chunks, 8 CTA syncs/step); register double-buffered
// ldsm/mma; xproj (fp16) prefetch hoisted above the per-mh 64-CTA barrier.
// ---------------------------------------------------------------------------
__global__ __launch_bounds__(128) void scan_kernel(float* __restrict__ final_out) {
    extern __shared__ char smem[];
    const uint32_t sb = smem_u32(smem);
    const int tid = threadIdx.x, wid = tid >> 5, lane = tid & 31;
    const int nt = blockIdx.x, mh = blockIdx.y;
    const int n0 = nt * 32;
    const int m0 = mh * 64;

    // ---- load resident W^T slice (32 rows x 2048 k), pitch 4112 ----
    {
        const __half* Wg = g_wr + (size_t)n0 * H_DIM;
        #pragma unroll 4
        for (int idx = tid; idx < 32 * 256; idx += 128) {      // 16B units
            int r = idx >> 8, kc = idx & 255;
            cp16(sb + r * WPITCH + kc * 16, Wg + (size_t)r * H_DIM + kc * 8);
        }
        cp_commit();
        cp_wait0();
        __syncthreads();
    }

    const int wm = wid >> 1, wn = wid & 1;
    const uint32_t aOff   = (uint32_t)((lane & 15) * ROWB3 + (lane >> 4) * 16);
    const uint32_t rowsel = (uint32_t)((lane & 7) | ((lane >> 1) & 8));
    const uint32_t bOffH  = rowsel * WPITCH + (lane & 8) * 2 + (uint32_t)(wn * 16) * WPITCH;

    const int er  = m0 + wm * 32 + (lane >> 2);
    const int ecc = n0 + wn * 16 + 2 * (lane & 3);
    const size_t eo00 = (size_t)er * H_DIM + ecc;              // (mi=0, ni=0)

    // ---- prefetch xproj fragment for t=0 (fp16 -> fp32 regs) ----
    float2 xf[2][2][2];
    {
        const __half* __restrict__ xp0 = g_xproj;
        #pragma unroll
        for (int mi = 0; mi < 2; mi++)
            #pragma unroll
            for (int ni = 0; ni < 2; ni++) {
                size_t o0 = eo00 + (size_t)(mi * 16) * H_DIM + ni * 8;
                xf[mi][ni][0] = __half22float2(__ldg((const __half2*)(xp0 + o0)));
                xf[mi][ni][1] = __half22float2(__ldg((const __half2*)(xp0 + o0 + (size_t)8 * H_DIM)));
            }
    }

    for (int t = 0; t < T_STEPS; t++) {
        const __half* __restrict__ Ahg = g_h[t & 1] + (size_t)m0 * H_DIM;

        float c[2][2][4];
        #pragma unroll
        for (int i = 0; i < 2; i++)
            #pragma unroll
            for (int j = 0; j < 2; j++)
                #pragma unroll
                for (int q = 0; q < 4; q++) c[i][j][q] = 0.0f;

        auto load_stage = [&](int s, int cch) {
            const int k0 = cch * KC3;
            uint32_t base = sb + WH_SZ + s * ST_SZ;
            #pragma unroll
            for (int j = 0; j < 16; j++) {         // h: 64 rows x 32 chunks of 16B
                int idx = tid + j * 128;
                int r = idx >> 5, kc = idx & 31;
                cp16(base + r * ROWB3 + kc * 16,
                     Ahg + (size_t)r * H_DIM + k0 + kc * 8);
            }
            cp_commit();
        };

        auto compute_stage = [&](int s, int cch) {
            uint32_t base = sb + WH_SZ + s * ST_SZ;
            uint32_t aA = base + (uint32_t)(wm * 32) * ROWB3 + aOff;
            uint32_t bH = sb + bOffH + (uint32_t)(cch * KC3) * 2;
            uint32_t ah[2][2][4], bh[2][4];
            ldsm4(aA, ah[0][0]);
            ldsm4(aA + 16 * ROWB3, ah[0][1]);
            ldsm4(bH, bh[0]);
            #pragma unroll
            for (int kk = 0; kk < KC3 / 16; kk++) {
                int cur = kk & 1, nxt = cur ^ 1;
                if (kk + 1 < KC3 / 16) {           // prefetch next k16 fragments
                    ldsm4(aA + (kk + 1) * 32, ah[nxt][0]);
                    ldsm4(aA + 16 * ROWB3 + (kk + 1) * 32, ah[nxt][1]);
                    ldsm4(bH + (kk + 1) * 32, bh[nxt]);
                }
                #pragma unroll
                for (int mi = 0; mi < 2; mi++)
                    #pragma unroll
                    for (int ni = 0; ni < 2; ni++)
                        mma16816(c[mi][ni], ah[cur][mi], bh[cur][2 * ni], bh[cur][2 * ni + 1]);
            }
        };

        // ---- 2-stage pipeline, one sync per chunk, wait0 exact ----
        load_stage(0, 0);
        #pragma unroll 1
        for (int cch = 0; cch < NCH3; cch++) {
            cp_wait0();
            __syncthreads();
            if (cch + 1 < NCH3) load_stage((cch + 1) & 1, cch + 1);
            compute_stage(cch & 1, cch);
        }

        // ---- epilogue: tanh(acc + xproj_t) -> h fp16 (or final fp32) ----
        const bool last = (t == T_STEPS - 1);
        __half* __restrict__ Hn = g_h[(t + 1) & 1];

        #pragma unroll
        for (int mi = 0; mi < 2; mi++)
            #pragma unroll
            for (int ni = 0; ni < 2; ni++) {
                size_t o0 = eo00 + (size_t)(mi * 16) * H_DIM + ni * 8;
                size_t o1 = o0 + (size_t)8 * H_DIM;
                float2 x0 = xf[mi][ni][0];
                float2 x1 = xf[mi][ni][1];
                float v00 = fast_tanh(c[mi][ni][0] + x0.x);
                float v01 = fast_tanh(c[mi][ni][1] + x0.y);
                float v10 = fast_tanh(c[mi][ni][2] + x1.x);
                float v11 = fast_tanh(c[mi][ni][3] + x1.y);
                if (last) {
                    *(float2*)(final_out + o0) = make_float2(v00, v01);
                    *(float2*)(final_out + o1) = make_float2(v10, v11);
                } else {
                    *(__half2*)(Hn + o0) = __floats2half2_rn(v00, v01);
                    *(__half2*)(Hn + o1) = __floats2half2_rn(v10, v11);
                }
            }

        if (!last) {
            // ---- prefetch xproj for t+1 BEFORE the barrier (h-independent) ----
            const __half* __restrict__ xpn = g_xproj + (size_t)(t + 1) * B_DIM * H_DIM;
            #pragma unroll
            for (int mi = 0; mi < 2; mi++)
                #pragma unroll
                for (int ni = 0; ni < 2; ni++) {
                    size_t o0 = eo00 + (size_t)(mi * 16) * H_DIM + ni * 8;
                    xf[mi][ni][0] = __half22float2(__ldg((const __half2*)(xpn + o0)));
                    xf[mi][ni][1] = __half22float2(__ldg((const __half2*)(xpn + o0 + (size_t)8 * H_DIM)));
                }

            // ---- per-mh grid barrier (64 CTAs), release/acquire ----
            __syncthreads();
            if (tid == 0) {
                unsigned* bp = &g_bar[2 * t + mh];
                asm volatile("red.release.gpu.global.add.u32 [%0], %1;"
                             :: "l"(bp), "r"(1u) : "memory");
                unsigned v;
                do {
                    asm volatile("ld.acquire.gpu.global.u32 %0, [%1];"
                                 : "=r"(v) : "l"(bp) : "memory");
                } while (v < 64u);
            }
            __syncthreads();
        }
    }
}

// ---------------------------------------------------------------------------
// Host launch — plain kernel launches only, graph-capturable
// ---------------------------------------------------------------------------
extern "C" void kernel_launch(void* const* d_in, const int* in_sizes, int n_in,
                              void* d_out, int out_size)
{
    const float* x     = (const float*)d_in[0];
    const float* w_in  = (const float*)d_in[1];
    const float* w_rec = (const float*)d_in[2];
    const float* bias  = (const float*)d_in[3];
    float* out = (float*)d_out;

    cudaFuncSetAttribute(scan_kernel,
                         cudaFuncAttributeMaxDynamicSharedMemorySize, SMEM_SCAN);
    cudaFuncSetAttribute(xproj_mma_kernel,
                         cudaFuncAttributeMaxDynamicSharedMemorySize, SMEM_XPROJ);

    // prep
    init_h0_kernel<<<(B_DIM * H_DIM + 255) / 256, 256>>>();
    conv_x_kernel<<<(int)(((size_t)T_STEPS * B_DIM * H_DIM) / 8 / 256), 256>>>(x);
    wtrans2_kernel<<<dim3(H_DIM / 32, H_DIM / 32, 2), dim3(32, 8)>>>(w_rec, w_in);

    // xproj (tensor-core, 1-product fp16; fp16 output)
    xproj_mma_kernel<<<dim3(H_DIM / 64, (T_STEPS * B_DIM) / 128), 256, SMEM_XPROJ>>>(bias);

    // persistent scan: all 256 steps in one launch
    scan_kernel<<<dim3(H_DIM / 32, B_DIM / 64), 128, SMEM_SCAN>>>(out);
}

// round 14
// speedup vs baseline: 1.5841x; 1.0476x over previous
#include <cuda_runtime.h>
#include <cuda_fp16.h>
#include <math.h>
#include <stdint.h>

#define T_STEPS 256
#define B_DIM   128
#define H_DIM   2048

// ---- xproj tiling (KC=64, 2-stage) ----
#define KC      64
#define NCH     (H_DIM / KC)       // 32
#define ROWB    144                // 64 fp16 + 16B pad

// ---- scan tiling (KC3=256, 2-stage) ----
#define KC3     256
#define NCH3    (H_DIM / KC3)      // 8
#define ROWB3   528                // 256 fp16 + 16B pad (4-bank row stagger)

// ---- persistent scan kernel smem ----
#define WPITCH   4112              // 2048*2 + 16 pad: conflict-free ldsm rows
#define WH_SZ    (32 * WPITCH)     // 131584 B resident W^T slice (fp16)
#define ST_SZ    (64 * ROWB3)      // 33792 B per h stage
#define SMEM_SCAN (WH_SZ + 2 * ST_SZ)   // 199168 (2-stage)

// ---- xproj kernel smem (1-product, 2-stage -> 4 CTAs/SM) ----
#define X_A   0                    // x tile (fp16): 128*144 = 18432
#define X_B   18432                // W_in: 64*144 = 9216
#define X_STG 27648
#define SMEM_XPROJ (2 * X_STG)     // 55296

// ---------------------------------------------------------------------------
// Device scratch (no allocations allowed anywhere)
// ---------------------------------------------------------------------------
__device__ __align__(128) __half g_xproj[(size_t)T_STEPS * B_DIM * H_DIM];  // 128 MB (fp16)
__device__ __align__(128) __half g_h[2][B_DIM * H_DIM];                     // fp16 hidden
__device__ __align__(128) __half g_wr[(size_t)H_DIM * H_DIM];               // w_rec^T fp16
__device__ __align__(128) __half g_wi[(size_t)H_DIM * H_DIM];               // w_in^T fp16
__device__ __align__(128) __half g_x[(size_t)T_STEPS * B_DIM * H_DIM];      // x fp16
__device__ unsigned g_bar[2 * T_STEPS];                                     // per-(t, mh) counters

// ---------------------------------------------------------------------------
// PTX helpers — legal on plain sm_103 target
// ---------------------------------------------------------------------------
__device__ __forceinline__ uint32_t smem_u32(const void* p) {
    uint32_t a;
    asm("{ .reg .u64 t; cvta.to.shared.u64 t, %1; cvt.u32.u64 %0, t; }"
        : "=r"(a) : "l"(p));
    return a;
}
__device__ __forceinline__ void cp16(uint32_t dst, const void* src) {
    asm volatile("cp.async.cg.shared.global [%0], [%1], 16;"
                 :: "r"(dst), "l"(src) : "memory");
}
__device__ __forceinline__ void cp_commit() {
    asm volatile("cp.async.commit_group;" ::: "memory");
}
__device__ __forceinline__ void cp_wait0() {
    asm volatile("cp.async.wait_group 0;" ::: "memory");
}
__device__ __forceinline__ void ldsm4(uint32_t addr, uint32_t r[4]) {
    asm volatile("ldmatrix.sync.aligned.m8n8.x4.shared.b16 {%0,%1,%2,%3}, [%4];"
                 : "=r"(r[0]), "=r"(r[1]), "=r"(r[2]), "=r"(r[3]) : "r"(addr));
}
__device__ __forceinline__ void mma16816(float c[4], const uint32_t a[4],
                                         uint32_t b0, uint32_t b1) {
    asm volatile("mma.sync.aligned.m16n8k16.row.col.f32.f16.f16.f32 "
                 "{%0,%1,%2,%3},{%4,%5,%6,%7},{%8,%9},{%0,%1,%2,%3};"
                 : "+f"(c[0]), "+f"(c[1]), "+f"(c[2]), "+f"(c[3])
                 : "r"(a[0]), "r"(a[1]), "r"(a[2]), "r"(a[3]), "r"(b0), "r"(b1));
}

// ---------------------------------------------------------------------------
// FMA-only accurate tanh, |err| ~2e-7
// ---------------------------------------------------------------------------
__device__ __forceinline__ float fast_tanh(float x) {
    float ax = fminf(fabsf(x), 9.0f);
    float t  = ax * 2.8853900817779268f;
    float f  = t + 12582912.0f;
    int   n  = __float_as_int(f) - 0x4B400000;
    float r  = t - (f - 12582912.0f);
    float p = 1.5403530e-4f;
    p = fmaf(p, r, 1.3333558e-3f);
    p = fmaf(p, r, 9.6181291e-3f);
    p = fmaf(p, r, 5.5504109e-2f);
    p = fmaf(p, r, 2.4022651e-1f);
    p = fmaf(p, r, 6.9314718e-1f);
    p = fmaf(p, r, 1.0f);
    float e2x = p * __int_as_float((n + 127) << 23);
    float d = e2x + 1.0f;
    float rc = __int_as_float(0x7EF311C3 - __float_as_int(d));
    rc = rc * fmaf(-d, rc, 2.0f);
    rc = rc * fmaf(-d, rc, 2.0f);
    rc = rc * fmaf(-d, rc, 2.0f);
    float y = fmaf(-2.0f, rc, 1.0f);
    return __int_as_float(__float_as_int(y) | (__float_as_int(x) & 0x80000000));
}

// ---------------------------------------------------------------------------
// Prep kernels
// ---------------------------------------------------------------------------
__global__ void init_h0_kernel() {
    int i = blockIdx.x * blockDim.x + threadIdx.x;
    if (i < B_DIM * H_DIM) g_h[0][i] = __float2half(0.0f);
    if (i < 2 * T_STEPS) g_bar[i] = 0u;
}

// x (fp32) -> fp16, 8 elems per thread
__global__ __launch_bounds__(256) void conv_x_kernel(const float* __restrict__ x) {
    size_t i = ((size_t)blockIdx.x * blockDim.x + threadIdx.x) * 8;
    float4 v0 = *(const float4*)(x + i);
    float4 v1 = *(const float4*)(x + i + 4);
    __half2 h0 = __floats2half2_rn(v0.x, v0.y);
    __half2 h1 = __floats2half2_rn(v0.z, v0.w);
    __half2 h2 = __floats2half2_rn(v1.x, v1.y);
    __half2 h3 = __floats2half2_rn(v1.z, v1.w);
    *(uint4*)(g_x + i) = make_uint4(
        *(uint32_t*)&h0, *(uint32_t*)&h1, *(uint32_t*)&h2, *(uint32_t*)&h3);
}

// Both weight transposes in one launch: z=0 -> w_rec->g_wr, z=1 -> w_in->g_wi.
// W (k,n) fp32 -> W^T (n,k) single fp16. 32x32 tiles.
__global__ __launch_bounds__(256) void wtrans2_kernel(
    const float* __restrict__ Wr, const float* __restrict__ Wi)
{
    __shared__ float tile[32][33];
    const float* __restrict__ W = blockIdx.z ? Wi : Wr;
    __half* __restrict__ d = blockIdx.z ? g_wi : g_wr;
    int tx = threadIdx.x, ty = threadIdx.y;
    int k0 = blockIdx.y * 32;
    int n0 = blockIdx.x * 32;
    #pragma unroll
    for (int j = 0; j < 32; j += 8)
        tile[ty + j][tx] = W[(size_t)(k0 + ty + j) * H_DIM + n0 + tx];
    __syncthreads();
    #pragma unroll
    for (int j = 0; j < 32; j += 8) {
        size_t idx = (size_t)(n0 + ty + j) * H_DIM + k0 + tx;
        d[idx] = __float2half(tile[tx][ty + j]);
    }
}

// ---------------------------------------------------------------------------
// xproj = X @ W_in + bias  (fp16 1-product HMMA, 2-stage pipeline, 4 CTA/SM)
// CTA tile 128x64, 8 warps (4m x 2n), warp tile 32x32. Grid (32, 256).
// Output stored as fp16.
// ---------------------------------------------------------------------------
__global__ __launch_bounds__(256) void xproj_mma_kernel(const float* __restrict__ bias) {
    extern __shared__ char smem[];
    const uint32_t sb = smem_u32(smem);
    const int tid = threadIdx.x, wid = tid >> 5, lane = tid & 31;
    const int m0 = blockIdx.y * 128;
    const int n0 = blockIdx.x * 64;

    const __half* __restrict__ A = g_x + (size_t)m0 * H_DIM;
    const __half* __restrict__ B = g_wi + (size_t)n0 * H_DIM;

    float c[2][4][4];
    #pragma unroll
    for (int i = 0; i < 2; i++)
        #pragma unroll
        for (int j = 0; j < 4; j++)
            #pragma unroll
            for (int q = 0; q < 4; q++) c[i][j][q] = 0.0f;

    auto load_stage = [&](int s, int cch) {
        const int k0 = cch * KC;
        uint32_t base = sb + s * X_STG;
        #pragma unroll
        for (int j = 0; j < 4; j++) {              // A: 128 rows x 8 chunks
            int idx = tid + j * 256;
            int r = idx >> 3, kc = idx & 7;
            cp16(base + X_A + r * ROWB + kc * 16, A + (size_t)r * H_DIM + k0 + kc * 8);
        }
        #pragma unroll
        for (int j = 0; j < 2; j++) {              // B: 64 rows x 8 chunks
            int idx = tid + j * 256;
            int r = idx >> 3, kc = idx & 7;
            cp16(base + X_B + r * ROWB + kc * 16, B + (size_t)r * H_DIM + k0 + kc * 8);
        }
        cp_commit();
    };

    const int mwb = (wid >> 1) * 32;
    const int nwb = (wid & 1) * 32;
    const uint32_t aOff = (uint32_t)((lane & 15) * ROWB + (lane >> 4) * 16);
    const uint32_t bOff = (uint32_t)(((lane & 7) | ((lane >> 1) & 8)) * ROWB + (lane & 8) * 2);

    auto compute_stage = [&](int s) {
        uint32_t base = sb + s * X_STG;
        uint32_t aA = base + X_A + mwb * ROWB + aOff;
        uint32_t bB = base + X_B + nwb * ROWB + bOff;
        uint32_t ah[2][2][4], bh[2][8];
        ldsm4(aA, ah[0][0]);
        ldsm4(aA + 16 * ROWB, ah[0][1]);
        ldsm4(bB, bh[0]);
        ldsm4(bB + 16 * ROWB, bh[0] + 4);
        #pragma unroll
        for (int kk = 0; kk < KC / 16; kk++) {
            int cur = kk & 1, nxt = cur ^ 1;
            if (kk + 1 < KC / 16) {                // prefetch next k16 fragments
                ldsm4(aA + (kk + 1) * 32, ah[nxt][0]);
                ldsm4(aA + 16 * ROWB + (kk + 1) * 32, ah[nxt][1]);
                ldsm4(bB + (kk + 1) * 32, bh[nxt]);
                ldsm4(bB + 16 * ROWB + (kk + 1) * 32, bh[nxt] + 4);
            }
            #pragma unroll
            for (int mi = 0; mi < 2; mi++)
                #pragma unroll
                for (int ni = 0; ni < 4; ni++)
                    mma16816(c[mi][ni], ah[cur][mi], bh[cur][2 * ni], bh[cur][2 * ni + 1]);
        }
    };

    // 2-stage pipeline: wait own chunk, issue next, compute
    load_stage(0, 0);
    #pragma unroll 1
    for (int cch = 0; cch < NCH; cch++) {
        cp_wait0();
        __syncthreads();
        if (cch + 1 < NCH) load_stage((cch + 1) & 1, cch + 1);
        compute_stage(cch & 1);
    }

    #pragma unroll
    for (int mi = 0; mi < 2; mi++)
        #pragma unroll
        for (int ni = 0; ni < 4; ni++) {
            int r  = m0 + mwb + mi * 16 + (lane >> 2);
            int cc = n0 + nwb + ni * 8 + 2 * (lane & 3);
            float bx = bias[cc], by = bias[cc + 1];
            size_t o0 = (size_t)r * H_DIM + cc;
            size_t o1 = o0 + (size_t)8 * H_DIM;
            *(__half2*)(g_xproj + o0) = __floats2half2_rn(c[mi][ni][0] + bx, c[mi][ni][1] + by);
            *(__half2*)(g_xproj + o1) = __floats2half2_rn(c[mi][ni][2] + bx, c[mi][ni][3] + by);
        }
}

// ---------------------------------------------------------------------------
// Persistent scan kernel (R10 structure — best measured): all 256 steps in
// ONE launch. Grid (64, 2) = 128 CTAs, 128 threads (4 warps, 2m x 2n, warp
// tile 32x16). W^T slice resident; h streamed via 2-stage cp.async pipeline
// (KC3=256 -> 8 chunks, 8 CTA syncs/step); register double-buffered
// ldsm/mma; xproj (fp16) prefetch hoisted above the per-mh 64-CTA barrier.
// ---------------------------------------------------------------------------
__global__ __launch_bounds__(128) void scan_kernel(float* __restrict__ final_out) {
    extern __shared__ char smem[];
    const uint32_t sb = smem_u32(smem);
    const int tid = threadIdx.x, wid = tid >> 5, lane = tid & 31;
    const int nt = blockIdx.x, mh = blockIdx.y;
    const int n0 = nt * 32;
    const int m0 = mh * 64;

    // ---- load resident W^T slice (32 rows x 2048 k), pitch 4112 ----
    {
        const __half* Wg = g_wr + (size_t)n0 * H_DIM;
        #pragma unroll 4
        for (int idx = tid; idx < 32 * 256; idx += 128) {      // 16B units
            int r = idx >> 8, kc = idx & 255;
            cp16(sb + r * WPITCH + kc * 16, Wg + (size_t)r * H_DIM + kc * 8);
        }
        cp_commit();
        cp_wait0();
        __syncthreads();
    }

    const int wm = wid >> 1, wn = wid & 1;
    const uint32_t aOff   = (uint32_t)((lane & 15) * ROWB3 + (lane >> 4) * 16);
    const uint32_t rowsel = (uint32_t)((lane & 7) | ((lane >> 1) & 8));
    const uint32_t bOffH  = rowsel * WPITCH + (lane & 8) * 2 + (uint32_t)(wn * 16) * WPITCH;

    const int er  = m0 + wm * 32 + (lane >> 2);
    const int ecc = n0 + wn * 16 + 2 * (lane & 3);
    const size_t eo00 = (size_t)er * H_DIM + ecc;              // (mi=0, ni=0)

    // ---- prefetch xproj fragment for t=0 (fp16 -> fp32 regs) ----
    float2 xf[2][2][2];
    {
        const __half* __restrict__ xp0 = g_xproj;
        #pragma unroll
        for (int mi = 0; mi < 2; mi++)
            #pragma unroll
            for (int ni = 0; ni < 2; ni++) {
                size_t o0 = eo00 + (size_t)(mi * 16) * H_DIM + ni * 8;
                xf[mi][ni][0] = __half22float2(__ldg((const __half2*)(xp0 + o0)));
                xf[mi][ni][1] = __half22float2(__ldg((const __half2*)(xp0 + o0 + (size_t)8 * H_DIM)));
            }
    }

    for (int t = 0; t < T_STEPS; t++) {
        const __half* __restrict__ Ahg = g_h[t & 1] + (size_t)m0 * H_DIM;

        float c[2][2][4];
        #pragma unroll
        for (int i = 0; i < 2; i++)
            #pragma unroll
            for (int j = 0; j < 2; j++)
                #pragma unroll
                for (int q = 0; q < 4; q++) c[i][j][q] = 0.0f;

        auto load_stage = [&](int s, int cch) {
            const int k0 = cch * KC3;
            uint32_t base = sb + WH_SZ + s * ST_SZ;
            #pragma unroll
            for (int j = 0; j < 16; j++) {         // h: 64 rows x 32 chunks of 16B
                int idx = tid + j * 128;
                int r = idx >> 5, kc = idx & 31;
                cp16(base + r * ROWB3 + kc * 16,
                     Ahg + (size_t)r * H_DIM + k0 + kc * 8);
            }
            cp_commit();
        };

        auto compute_stage = [&](int s, int cch) {
            uint32_t base = sb + WH_SZ + s * ST_SZ;
            uint32_t aA = base + (uint32_t)(wm * 32) * ROWB3 + aOff;
            uint32_t bH = sb + bOffH + (uint32_t)(cch * KC3) * 2;
            uint32_t ah[2][2][4], bh[2][4];
            ldsm4(aA, ah[0][0]);
            ldsm4(aA + 16 * ROWB3, ah[0][1]);
            ldsm4(bH, bh[0]);
            #pragma unroll
            for (int kk = 0; kk < KC3 / 16; kk++) {
                int cur = kk & 1, nxt = cur ^ 1;
                if (kk + 1 < KC3 / 16) {           // prefetch next k16 fragments
                    ldsm4(aA + (kk + 1) * 32, ah[nxt][0]);
                    ldsm4(aA + 16 * ROWB3 + (kk + 1) * 32, ah[nxt][1]);
                    ldsm4(bH + (kk + 1) * 32, bh[nxt]);
                }
                #pragma unroll
                for (int mi = 0; mi < 2; mi++)
                    #pragma unroll
                    for (int ni = 0; ni < 2; ni++)
                        mma16816(c[mi][ni], ah[cur][mi], bh[cur][2 * ni], bh[cur][2 * ni + 1]);
            }
        };

        // ---- 2-stage pipeline, one sync per chunk, wait0 exact ----
        load_stage(0, 0);
        #pragma unroll 1
        for (int cch = 0; cch < NCH3; cch++) {
            cp_wait0();
            __syncthreads();
            if (cch + 1 < NCH3) load_stage((cch + 1) & 1, cch + 1);
            compute_stage(cch & 1, cch);
        }

        // ---- epilogue: tanh(acc + xproj_t) -> h fp16 (or final fp32) ----
        const bool last = (t == T_STEPS - 1);
        __half* __restrict__ Hn = g_h[(t + 1) & 1];

        #pragma unroll
        for (int mi = 0; mi < 2; mi++)
            #pragma unroll
            for (int ni = 0; ni < 2; ni++) {
                size_t o0 = eo00 + (size_t)(mi * 16) * H_DIM + ni * 8;
                size_t o1 = o0 + (size_t)8 * H_DIM;
                float2 x0 = xf[mi][ni][0];
                float2 x1 = xf[mi][ni][1];
                float v00 = fast_tanh(c[mi][ni][0] + x0.x);
                float v01 = fast_tanh(c[mi][ni][1] + x0.y);
                float v10 = fast_tanh(c[mi][ni][2] + x1.x);
                float v11 = fast_tanh(c[mi][ni][3] + x1.y);
                if (last) {
                    *(float2*)(final_out + o0) = make_float2(v00, v01);
                    *(float2*)(final_out + o1) = make_float2(v10, v11);
                } else {
                    *(__half2*)(Hn + o0) = __floats2half2_rn(v00, v01);
                    *(__half2*)(Hn + o1) = __floats2half2_rn(v10, v11);
                }
            }

        if (!last) {
            // ---- prefetch xproj for t+1 BEFORE the barrier (h-independent) ----
            const __half* __restrict__ xpn = g_xproj + (size_t)(t + 1) * B_DIM * H_DIM;
            #pragma unroll
            for (int mi = 0; mi < 2; mi++)
                #pragma unroll
                for (int ni = 0; ni < 2; ni++) {
                    size_t o0 = eo00 + (size_t)(mi * 16) * H_DIM + ni * 8;
                    xf[mi][ni][0] = __half22float2(__ldg((const __half2*)(xpn + o0)));
                    xf[mi][ni][1] = __half22float2(__ldg((const __half2*)(xpn + o0 + (size_t)8 * H_DIM)));
                }

            // ---- per-mh grid barrier (64 CTAs), release/acquire ----
            __syncthreads();
            if (tid == 0) {
                unsigned* bp = &g_bar[2 * t + mh];
                asm volatile("red.release.gpu.global.add.u32 [%0], %1;"
                             :: "l"(bp), "r"(1u) : "memory");
                unsigned v;
                do {
                    asm volatile("ld.acquire.gpu.global.u32 %0, [%1];"
                                 : "=r"(v) : "l"(bp) : "memory");
                } while (v < 64u);
            }
            __syncthreads();
        }
    }
}

// ---------------------------------------------------------------------------
// Host launch — plain kernel launches only, graph-capturable
// ---------------------------------------------------------------------------
extern "C" void kernel_launch(void* const* d_in, const int* in_sizes, int n_in,
                              void* d_out, int out_size)
{
    const float* x     = (const float*)d_in[0];
    const float* w_in  = (const float*)d_in[1];
    const float* w_rec = (const float*)d_in[2];
    const float* bias  = (const float*)d_in[3];
    float* out = (float*)d_out;

    cudaFuncSetAttribute(scan_kernel,
                         cudaFuncAttributeMaxDynamicSharedMemorySize, SMEM_SCAN);
    cudaFuncSetAttribute(xproj_mma_kernel,
                         cudaFuncAttributeMaxDynamicSharedMemorySize, SMEM_XPROJ);

    // prep
    init_h0_kernel<<<(B_DIM * H_DIM + 255) / 256, 256>>>();
    conv_x_kernel<<<(int)(((size_t)T_STEPS * B_DIM * H_DIM) / 8 / 256), 256>>>(x);
    wtrans2_kernel<<<dim3(H_DIM / 32, H_DIM / 32, 2), dim3(32, 8)>>>(w_rec, w_in);

    // xproj (tensor-core, 1-product fp16; fp16 output; 2-stage, 4 CTA/SM)
    xproj_mma_kernel<<<dim3(H_DIM / 64, (T_STEPS * B_DIM) / 128), 256, SMEM_XPROJ>>>(bias);

    // persistent scan: all 256 steps in one launch
    scan_kernel<<<dim3(H_DIM / 32, B_DIM / 64), 128, SMEM_SCAN>>>(out);
}